// round 14
// baseline (speedup 1.0000x reference)
#include <cuda_runtime.h>
#include <math_constants.h>

#define B 32
#define H0 256
#define W0 256
#define NPIX (B*H0*W0)
#define BN_EPS 1e-3f

typedef unsigned long long u64t;

__device__ __forceinline__ u64t pk2(float a, float b) {
    u64t r; asm("mov.b64 %0,{%1,%2};" : "=l"(r) : "f"(a), "f"(b)); return r;
}
__device__ __forceinline__ void upk2(u64t v, float& a, float& b) {
    asm("mov.b64 {%0,%1},%2;" : "=f"(a), "=f"(b) : "l"(v));
}
__device__ __forceinline__ void fma2(u64t& d, u64t a, u64t b) {
    asm("fma.rn.f32x2 %0,%1,%2,%0;" : "+l"(d) : "l"(a), "l"(b));
}
__device__ __forceinline__ unsigned tf32r(float v) {
    unsigned r; asm("cvt.rna.tf32.f32 %0,%1;" : "=r"(r) : "f"(v)); return r;
}
#define MMA_TF32(d, a0,a1,a2,a3, b0,b1) \
    asm volatile("mma.sync.aligned.m16n8k8.row.col.f32.tf32.tf32.f32 " \
        "{%0,%1,%2,%3},{%4,%5,%6,%7},{%8,%9},{%0,%1,%2,%3};" \
        : "+f"((d)[0]),"+f"((d)[1]),"+f"((d)[2]),"+f"((d)[3]) \
        : "r"(a0),"r"(a1),"r"(a2),"r"(a3),"r"(b0),"r"(b1))

// ---------------- scratch ----------------
__device__ float g_MA[NPIX];
__device__ float g_MB[NPIX];
__device__ float g_XC[NPIX];
__device__ float g_Y1[(size_t)B*8*254*254];
__device__ float g_Y2[(size_t)B*16*126*126];
__device__ float g_Y3[(size_t)B*32*124*124];
__device__ float g_GM[B*32];
__device__ float g_H[B];
__device__ unsigned g_WP2[1152];
__device__ unsigned g_WP3[4608];
__device__ unsigned g_WP4[9216];

// ---------------- merged weight packing + GM zero (one launch) ----------------
__global__ void packall_k(const float* __restrict__ w2, const float* __restrict__ w3,
                          const float* __restrict__ w4,
                          unsigned* __restrict__ WP2, unsigned* __restrict__ WP3,
                          unsigned* __restrict__ WP4, float* __restrict__ GM) {
    int gidx = threadIdx.x + blockIdx.x*256;
    if (gidx < 1152) {
        int idx = gidx;
        int val = idx & 3; int knb = val >> 1, kkh = val & 1;
        int ln  = (idx >> 2) & 31; int lkq = ln & 3, lnr = ln >> 2;
        int tap = idx >> 7;
        int ci = lkq + 4*kkh;
        int co = knb*8 + lnr;
        WP2[idx] = tf32r(w2[tap*128 + ci*16 + co]);
    } else if (gidx < 1152 + 4608) {
        int idx = gidx - 1152;
        int val = idx & 7; int knb = val >> 1, kkh = val & 1;
        int ln  = (idx >> 3) & 31; int lkq = ln & 3, lnr = ln >> 2;
        int rest = idx >> 8;
        int cib = rest & 1; int t2 = rest >> 1;
        int tap = t2 % 9, cc = t2 / 9;
        int ci = cc*16 + cib*8 + lkq + 4*kkh;
        int co = knb*8 + lnr;
        WP3[idx] = tf32r(w3[tap*(16*32) + ci*32 + co]);
    } else if (gidx < 1152 + 4608 + 9216) {
        int idx = gidx - 5760;
        int val = idx & 7; int knb = val >> 1, kkh = val & 1;
        int ln  = (idx >> 3) & 31; int lkq = ln & 3, lnr = ln >> 2;
        int rest = idx >> 8;
        int cib = rest & 1; int t2 = rest >> 1;
        int tap = t2 % 9, cc = t2 / 9;
        int ci = cc*16 + cib*8 + lkq + 4*kkh;
        int co = knb*8 + lnr;
        WP4[idx] = tf32r(w4[tap*(32*32) + ci*32 + co]);
    } else if (gidx < 1152 + 4608 + 9216 + B*32) {
        GM[gidx - 14976] = 0.f;
    }
}

// ---------------- fused 4-pass morphology: E(ko),D(ko),D(kc),E(kc), halo 4 ----------------
#define MT 64
#define MHL 4
#define MS (MT + 2*MHL)
#define MCELL (MS*MS)
#define MNIT ((MCELL + 255)/256)
__global__ __launch_bounds__(256)
void morph4_k(const float* __restrict__ x, float* __restrict__ xc,
              const float* __restrict__ ko, const float* __restrict__ kc) {
    __shared__ float sm[2][MCELL];
    __shared__ float sk[18];
    int t = threadIdx.x;
    if (t < 18) sk[t] = (t < 9) ? ko[t] : kc[t - 9];
    int ox = blockIdx.x*MT - MHL;
    int oy = blockIdx.y*MT - MHL;
    const size_t boff = (size_t)blockIdx.z*H0*W0;

    bool inb[MNIT], inter[MNIT];
#pragma unroll
    for (int k = 0; k < MNIT; k++) {
        int i = t + k*256;
        bool ib = false, it = false;
        if (i < MCELL) {
            int ly = i / MS, lx = i % MS;
            int gy = oy + ly, gx = ox + lx;
            ib = (gy >= 0 && gy < H0 && gx >= 0 && gx < W0);
            sm[0][i] = ib ? x[boff + gy*W0 + gx] : CUDART_INF_F;
            it = (ly > 0 && ly < MS-1 && lx > 0 && lx < MS-1);
        }
        inb[k] = ib; inter[k] = it;
    }
    __syncthreads();
    int cur = 0;
#pragma unroll
    for (int op = 0; op < 4; op++) {
        const bool ero = (op == 0 || op == 3);
        const int koff = (op < 2) ? 0 : 9;
        const float nextpad = (op >= 2) ? CUDART_INF_F : -CUDART_INF_F;
#pragma unroll
        for (int k = 0; k < MNIT; k++) {
            int i = t + k*256;
            if (i < MCELL) {
                float v;
                if (!inb[k]) {
                    v = nextpad;
                } else if (inter[k]) {
                    const float* s0 = &sm[cur][i];
                    if (ero) {
                        float m = s0[-MS-1] - sk[koff + 8];
                        m = fminf(m, s0[-MS  ] - sk[koff + 7]);
                        m = fminf(m, s0[-MS+1] - sk[koff + 6]);
                        m = fminf(m, s0[-1]    - sk[koff + 5]);
                        m = fminf(m, s0[0]     - sk[koff + 4]);
                        m = fminf(m, s0[1]     - sk[koff + 3]);
                        m = fminf(m, s0[MS-1]  - sk[koff + 2]);
                        m = fminf(m, s0[MS  ]  - sk[koff + 1]);
                        m = fminf(m, s0[MS+1]  - sk[koff + 0]);
                        v = m;
                    } else {
                        float m = s0[-MS-1] + sk[koff + 0];
                        m = fmaxf(m, s0[-MS  ] + sk[koff + 1]);
                        m = fmaxf(m, s0[-MS+1] + sk[koff + 2]);
                        m = fmaxf(m, s0[-1]    + sk[koff + 3]);
                        m = fmaxf(m, s0[0]     + sk[koff + 4]);
                        m = fmaxf(m, s0[1]     + sk[koff + 5]);
                        m = fmaxf(m, s0[MS-1]  + sk[koff + 6]);
                        m = fmaxf(m, s0[MS  ]  + sk[koff + 7]);
                        m = fmaxf(m, s0[MS+1]  + sk[koff + 8]);
                        v = m;
                    }
                } else {
                    v = sm[cur][i];
                }
                sm[1-cur][i] = v;
            }
        }
        __syncthreads();
        cur ^= 1;
    }
    int tx = t & 63, tyq = t >> 6;
#pragma unroll
    for (int k = 0; k < 16; k++) {
        int r = tyq + 4*k;
        xc[boff + (size_t)(oy + MHL + r)*W0 + (ox + MHL + tx)] =
            sm[cur][(r + MHL)*MS + (tx + MHL)];
    }
}

// ---------------- conv1 (1->8) + relu + bn1 ----------------
__global__ void conv1_k(const float* __restrict__ xc, const float* __restrict__ w,
                        const float* __restrict__ bias,
                        const float* __restrict__ gg, const float* __restrict__ bb,
                        const float* __restrict__ mm, const float* __restrict__ vv,
                        float* __restrict__ out) {
    __shared__ float ws[72];
    int t = threadIdx.x;
    if (t < 72) ws[t] = w[t];
    __syncthreads();
    int y = blockIdx.x, b = blockIdx.y;
    int x = t;
    if (x >= 254) return;
    const float* base = xc + ((size_t)b*H0 + y)*W0 + x;
    u64t acc[4];
#pragma unroll
    for (int p = 0; p < 4; p++) acc[p] = pk2(bias[2*p], bias[2*p+1]);
#pragma unroll
    for (int tap = 0; tap < 9; tap++) {
        float v = base[(tap/3)*W0 + (tap%3)];
        u64t pv = pk2(v, v);
        const u64t* wq = (const u64t*)(ws + tap*8);
#pragma unroll
        for (int p = 0; p < 4; p++) fma2(acc[p], pv, wq[p]);
    }
#pragma unroll
    for (int p = 0; p < 4; p++) {
        float a0, a1; upk2(acc[p], a0, a1);
        int k0 = 2*p, k1 = 2*p+1;
        float s0 = gg[k0] * rsqrtf(vv[k0] + BN_EPS);
        float s1 = gg[k1] * rsqrtf(vv[k1] + BN_EPS);
        out[((size_t)(b*8 + k0)*254 + y)*254 + x] = s0*(fmaxf(a0,0.f) - mm[k0]) + bb[k0];
        out[((size_t)(b*8 + k1)*254 + y)*254 + x] = s1*(fmaxf(a1,0.f) - mm[k1]) + bb[k1];
    }
}

// ---------------- conv3/conv4: tensor tf32, TW=32, CO=32 ----------------
template<int CI, int HIN, int WIN, int MODE>
__global__ __launch_bounds__(256)
void tconv_k(const float* __restrict__ gin, const unsigned* __restrict__ gwp,
             const float* __restrict__ gb,
             const float* __restrict__ bng, const float* __restrict__ bnb,
             const float* __restrict__ bnm, const float* __restrict__ bnv,
             float* __restrict__ gout) {
    constexpr int CO = 32;
    constexpr int HOUT = HIN - 2, WOUT = WIN - 2;
    constexpr int CC  = 16;
    constexpr int NCH = CI / CC;
    constexpr int STR = 36, PLANE = 360;

    __shared__ __align__(16) unsigned in_s[CC*PLANE];
    __shared__ __align__(16) unsigned wp_s[4608];
    __shared__ float smax[CO];

    int tid = threadIdx.x;
    int warp = tid >> 5, lane = tid & 31;
    int kq = lane & 3, nr = lane >> 2;
    int ox0 = blockIdx.x * 32, oy0 = blockIdx.y * 8;
    int b = blockIdx.z;

    const bool interior = (oy0 + 10 <= HIN) && (ox0 + 34 <= WIN);

    if (MODE == 2 && tid < CO) smax[tid] = 0.f;

    float acc[2][4][4];
#pragma unroll
    for (int j = 0; j < 2; j++)
#pragma unroll
        for (int nb = 0; nb < 4; nb++)
#pragma unroll
            for (int q = 0; q < 4; q++) acc[j][nb][q] = 0.f;

    for (int cc = 0; cc < NCH; cc++) {
        __syncthreads();
        for (int i = tid; i < 1152; i += 256)
            *(uint4*)&wp_s[i*4] = __ldg((const uint4*)(gwp + cc*4608 + i*4));
        if (interior) {
#pragma unroll
            for (int it = 0; it < 20; it++) {
                int rowid = it*8 + warp;
                int ci = rowid / 10, yy = rowid - ci*10;
                if (lane < 17) {
                    float2 g = *((const float2*)(gin +
                        ((size_t)(b*CI + cc*CC + ci)*HIN + oy0 + yy)*WIN + ox0) + lane);
                    uint2 u; u.x = tf32r(g.x); u.y = tf32r(g.y);
                    *(uint2*)&in_s[ci*PLANE + yy*STR + lane*2] = u;
                }
            }
        } else {
            for (int idx = tid; idx < CC*340; idx += 256) {
                int ci = idx / 340, rem = idx % 340;
                int yy = rem / 34, xx = rem % 34;
                int gy = oy0 + yy, gx = ox0 + xx;
                float v = 0.f;
                if (gy < HIN && gx < WIN)
                    v = gin[((size_t)(b*CI + cc*CC + ci)*HIN + gy)*WIN + gx];
                in_s[ci*PLANE + yy*STR + xx] = tf32r(v);
            }
        }
        __syncthreads();
#pragma unroll
        for (int tap = 0; tap < 9; tap++) {
            const int dy = tap/3, dx = tap%3;
#pragma unroll
            for (int cib = 0; cib < 2; cib++) {
                const uint4* wq = (const uint4*)(wp_s + ((tap*2 + cib)*32 + lane)*8);
                uint4 b01 = wq[0];
                uint4 b23 = wq[1];
                const unsigned* ia = in_s + (cib*8 + kq)*PLANE + (warp+dy)*STR + dx + nr;
#pragma unroll
                for (int j = 0; j < 2; j++) {
                    unsigned a0 = ia[j*16];
                    unsigned a1 = ia[j*16 + 8];
                    unsigned a2 = ia[j*16 + 4*PLANE];
                    unsigned a3 = ia[j*16 + 4*PLANE + 8];
                    MMA_TF32(acc[j][0], a0, a1, a2, a3, b01.x, b01.y);
                    MMA_TF32(acc[j][1], a0, a1, a2, a3, b01.z, b01.w);
                    MMA_TF32(acc[j][2], a0, a1, a2, a3, b23.x, b23.y);
                    MMA_TF32(acc[j][3], a0, a1, a2, a3, b23.z, b23.w);
                }
            }
        }
    }

    int y = oy0 + warp;
    float biA[4], biB[4];
#pragma unroll
    for (int nb = 0; nb < 4; nb++) {
        biA[nb] = gb[nb*8 + 2*kq];
        biB[nb] = gb[nb*8 + 2*kq + 1];
    }

    if (MODE == 2) {
        float lm[4][2];
#pragma unroll
        for (int nb = 0; nb < 4; nb++) { lm[nb][0] = 0.f; lm[nb][1] = 0.f; }
        if (y < HOUT) {
#pragma unroll
            for (int j = 0; j < 2; j++) {
                int xA = ox0 + j*16 + nr;
                int xB = xA + 8;
#pragma unroll
                for (int nb = 0; nb < 4; nb++) {
                    if (xA < WOUT) {
                        lm[nb][0] = fmaxf(lm[nb][0], acc[j][nb][0] + biA[nb]);
                        lm[nb][1] = fmaxf(lm[nb][1], acc[j][nb][1] + biB[nb]);
                    }
                    if (xB < WOUT) {
                        lm[nb][0] = fmaxf(lm[nb][0], acc[j][nb][2] + biA[nb]);
                        lm[nb][1] = fmaxf(lm[nb][1], acc[j][nb][3] + biB[nb]);
                    }
                }
            }
        }
#pragma unroll
        for (int nb = 0; nb < 4; nb++) {
            atomicMax((int*)&smax[nb*8 + 2*kq],     __float_as_int(fmaxf(lm[nb][0], 0.f)));
            atomicMax((int*)&smax[nb*8 + 2*kq + 1], __float_as_int(fmaxf(lm[nb][1], 0.f)));
        }
        __syncthreads();
        if (tid < CO)
            atomicMax((int*)&gout[b*CO + tid], __float_as_int(smax[tid]));
    } else {
        if (y < HOUT) {
#pragma unroll
            for (int nb = 0; nb < 4; nb++) {
                int coA = nb*8 + 2*kq, coB = coA + 1;
                float scA = bng[coA] * rsqrtf(bnv[coA] + BN_EPS);
                float scB = bng[coB] * rsqrtf(bnv[coB] + BN_EPS);
                float sbA = bnb[coA], sbB = bnb[coB];
                float smA = bnm[coA], smB = bnm[coB];
                float* pA = gout + ((size_t)(b*CO + coA)*HOUT + y)*WOUT;
                float* pB = gout + ((size_t)(b*CO + coB)*HOUT + y)*WOUT;
#pragma unroll
                for (int j = 0; j < 2; j++) {
                    int xA = ox0 + j*16 + nr;
                    int xB = xA + 8;
                    if (xA < WOUT) {
                        pA[xA] = scA*(fmaxf(acc[j][nb][0] + biA[nb], 0.f) - smA) + sbA;
                        pB[xA] = scB*(fmaxf(acc[j][nb][1] + biB[nb], 0.f) - smB) + sbB;
                    }
                    if (xB < WOUT) {
                        pA[xB] = scA*(fmaxf(acc[j][nb][2] + biA[nb], 0.f) - smA) + sbA;
                        pB[xB] = scB*(fmaxf(acc[j][nb][3] + biB[nb], 0.f) - smB) + sbB;
                    }
                }
            }
        }
    }
}

// ---------------- conv2 tensor: CI=8, CO=16, TW=64, fused maxpool2+bn ----------------
#define T2STR   68
#define T2PLANE 680
__global__ __launch_bounds__(256)
void tconv2_k(const float* __restrict__ gin, const unsigned* __restrict__ gwp,
              const float* __restrict__ gb,
              const float* __restrict__ bng, const float* __restrict__ bnb,
              const float* __restrict__ bnm, const float* __restrict__ bnv,
              float* __restrict__ gout) {
    constexpr int CI = 8, CO = 16;
    constexpr int HIN = 254, WIN = 254;
    constexpr int HOUT = 252, WOUT = 252;
    constexpr int LW = 66;

    __shared__ __align__(16) unsigned shm2[8192];
    __shared__ __align__(16) unsigned wp_s[1152];
    unsigned* in_s = shm2;
    float* pool_s  = (float*)shm2;

    int tid = threadIdx.x;
    int warp = tid >> 5, lane = tid & 31;
    int kq = lane & 3, nr = lane >> 2;
    int ox0 = blockIdx.x * 64, oy0 = blockIdx.y * 8;
    int b = blockIdx.z;

    const bool interior = (oy0 + 10 <= HIN) && (ox0 + 66 <= WIN);

    float acc[4][2][4];
#pragma unroll
    for (int j = 0; j < 4; j++)
#pragma unroll
        for (int nb = 0; nb < 2; nb++)
#pragma unroll
            for (int q = 0; q < 4; q++) acc[j][nb][q] = 0.f;

    for (int i = tid; i < 288; i += 256)
        if (i < 288) *(uint4*)&wp_s[i*4] = __ldg((const uint4*)(gwp + i*4));

    if (interior) {
#pragma unroll
        for (int it = 0; it < 10; it++) {
            int rowid = it*8 + warp;
            int ci = rowid / 10, yy = rowid - ci*10;
            const float* gr = gin + ((size_t)(b*CI + ci)*HIN + oy0 + yy)*WIN + ox0;
            unsigned* sr = in_s + ci*T2PLANE + yy*T2STR;
            float2 g = *(const float2*)(gr + lane*2);
            uint2 u; u.x = tf32r(g.x); u.y = tf32r(g.y);
            *(uint2*)&sr[lane*2] = u;
            if (lane == 0) {
                float2 g2 = *(const float2*)(gr + 64);
                uint2 u2; u2.x = tf32r(g2.x); u2.y = tf32r(g2.y);
                *(uint2*)&sr[64] = u2;
            }
        }
    } else {
        for (int idx = tid; idx < CI*10*LW; idx += 256) {
            int ci = idx / (10*LW), rem = idx % (10*LW);
            int yy = rem / LW, xx = rem % LW;
            int gy = oy0 + yy, gx = ox0 + xx;
            float v = 0.f;
            if (gy < HIN && gx < WIN)
                v = gin[((size_t)(b*CI + ci)*HIN + gy)*WIN + gx];
            in_s[ci*T2PLANE + yy*T2STR + xx] = tf32r(v);
        }
    }
    __syncthreads();
#pragma unroll
    for (int tap = 0; tap < 9; tap++) {
        const int dy = tap/3, dx = tap%3;
        uint4 bq = *(const uint4*)(wp_s + (tap*32 + lane)*4);
        const unsigned* ia = in_s + kq*T2PLANE + (warp+dy)*T2STR + dx + nr;
#pragma unroll
        for (int j = 0; j < 4; j++) {
            unsigned a0 = ia[j*16];
            unsigned a1 = ia[j*16 + 8];
            unsigned a2 = ia[j*16 + 4*T2PLANE];
            unsigned a3 = ia[j*16 + 4*T2PLANE + 8];
            MMA_TF32(acc[j][0], a0, a1, a2, a3, bq.x, bq.y);
            MMA_TF32(acc[j][1], a0, a1, a2, a3, bq.z, bq.w);
        }
    }

    float biA[2], biB[2];
#pragma unroll
    for (int nb = 0; nb < 2; nb++) {
        biA[nb] = gb[nb*8 + 2*kq];
        biB[nb] = gb[nb*8 + 2*kq + 1];
    }
    __syncthreads();
#pragma unroll
    for (int j = 0; j < 4; j++) {
        int xA = j*16 + nr, xB = xA + 8;
#pragma unroll
        for (int nb = 0; nb < 2; nb++) {
            int coA = nb*8 + 2*kq, coB = coA + 1;
            pool_s[warp*1024 + xA*16 + coA] = fmaxf(acc[j][nb][0] + biA[nb], 0.f);
            pool_s[warp*1024 + xA*16 + coB] = fmaxf(acc[j][nb][1] + biB[nb], 0.f);
            pool_s[warp*1024 + xB*16 + coA] = fmaxf(acc[j][nb][2] + biA[nb], 0.f);
            pool_s[warp*1024 + xB*16 + coB] = fmaxf(acc[j][nb][3] + biB[nb], 0.f);
        }
    }
    __syncthreads();

#pragma unroll
    for (int pid = tid; pid < 2048; pid += 256) {
        int co = pid & 15;
        int px = (pid >> 4) & 31;
        int py = pid >> 9;
        int base = (2*py)*1024 + (2*px)*16 + co;
        float v = fmaxf(fmaxf(pool_s[base], pool_s[base+16]),
                        fmaxf(pool_s[base+1024], pool_s[base+1040]));
        int gpy = (oy0 >> 1) + py;
        int gpx = (ox0 >> 1) + px;
        if (gpy < HOUT/2 && gpx < WOUT/2) {
            float sc = bng[co] * rsqrtf(bnv[co] + BN_EPS);
            v = sc*(v - bnm[co]) + bnb[co];
            gout[((size_t)(b*CO + co)*(HOUT/2) + gpy)*(WOUT/2) + gpx] = v;
        }
    }
}

// ---------------- dense ----------------
__global__ void dense_k(const float* __restrict__ gm, const float* __restrict__ dw,
                        const float* __restrict__ db, float* __restrict__ h,
                        float* __restrict__ out_tail) {
    int b = threadIdx.x;
    if (b >= B) return;
    float s = db[0];
#pragma unroll
    for (int c = 0; c < 32; c++) s = fmaf(gm[b*32 + c], dw[c], s);
    h[b] = s;
    out_tail[b] = s;
}

// ---------------- geodesic reconstruction: sliding-window + shfl, 5 steps ----------------
// tile 74x74 (halo 5), stride 76; 9 warps: 3 col-strips (0/30/60) x 3 row-bands (24 rows).
// Each warp: vertical 3-row max in registers (1 LDS/row), horizontal via shfl, mask LDS, STS.
// Ring (row/col 0,73) frozen: written into both buffers at init, never updated.
#define QRS 74
#define QST 76
#define QSH (3*QRS*QST*4)
template<bool INIT>
__global__ __launch_bounds__(288)
void recon_k(const float* __restrict__ src, const float* __restrict__ mask,
             const float* __restrict__ h, float* __restrict__ dst) {
    extern __shared__ float rsh[];
    float* Abuf = rsh;
    float* Bbuf = rsh + QRS*QST;
    float* Mbuf = rsh + 2*QRS*QST;
    int t = threadIdx.x;
    int ox = blockIdx.x*64 - 5;
    int oy = blockIdx.y*64 - 5;
    const size_t boff = (size_t)blockIdx.z*H0*W0;
    const float hv = INIT ? h[blockIdx.z] : 0.f;

    for (int i = t; i < QRS*QRS; i += 288) {
        int ly = i / QRS, lx = i % QRS;
        int gy = oy + ly, gx = ox + lx;
        float sv = -CUDART_INF_F, mv = -CUDART_INF_F;
        if (gy >= 0 && gy < H0 && gx >= 0 && gx < W0) {
            mv = mask[boff + gy*W0 + gx];
            sv = INIT ? (mv - hv) : src[boff + gy*W0 + gx];
        }
        Abuf[ly*QST + lx] = sv;
        Bbuf[ly*QST + lx] = sv;
        Mbuf[ly*QST + lx] = mv;
    }
    __syncthreads();

    int warp = t >> 5, lane = t & 31;
    int strip = warp % 3, band = warp / 3;
    int r0 = 1 + band*24;
    int col = strip*30 + lane;
    int cc  = (col < QRS) ? col : (QRS - 1);
    const bool wout = (lane >= 1 && lane <= 30 && col <= QRS - 2);

    float* curp = Abuf;
    float* nxtp = Bbuf;
#pragma unroll
    for (int step = 0; step < 5; step++) {
        float ap = curp[(r0-1)*QST + cc];
        float ac = curp[(r0  )*QST + cc];
#pragma unroll
        for (int rr = 0; rr < 24; rr++) {
            int r = r0 + rr;
            float an = curp[(r+1)*QST + cc];
            float vm = fmaxf(fmaxf(ap, ac), an);
            float vl = __shfl_up_sync(0xffffffffu, vm, 1);
            float vr = __shfl_down_sync(0xffffffffu, vm, 1);
            if (wout)
                nxtp[r*QST + col] =
                    fminf(fmaxf(fmaxf(vl, vm), vr), Mbuf[r*QST + col]);
            ap = ac; ac = an;
        }
        __syncthreads();
        float* tmp = curp; curp = nxtp; nxtp = tmp;
    }

    // store center 64x64 (tile rows/cols 5..68)
    for (int i = t; i < 4096; i += 288) {
        int r = 5 + (i >> 6), c = 5 + (i & 63);
        dst[boff + (size_t)(oy + r)*W0 + (ox + c)] = curp[r*QST + c];
    }
}

// ---------------- launch ----------------
extern "C" void kernel_launch(void* const* d_in, const int* in_sizes, int n_in,
                              void* d_out, int out_size) {
    const float* x    = (const float*)d_in[0];
    const float* ko   = (const float*)d_in[1];
    const float* kc   = (const float*)d_in[2];
    const float* w1   = (const float*)d_in[3];
    const float* b1   = (const float*)d_in[4];
    const float* w2   = (const float*)d_in[5];
    const float* b2   = (const float*)d_in[6];
    const float* w3   = (const float*)d_in[7];
    const float* b3   = (const float*)d_in[8];
    const float* w4   = (const float*)d_in[9];
    const float* b4   = (const float*)d_in[10];
    const float* bn1g = (const float*)d_in[11];
    const float* bn1b = (const float*)d_in[12];
    const float* bn1m = (const float*)d_in[13];
    const float* bn1v = (const float*)d_in[14];
    const float* bn2g = (const float*)d_in[15];
    const float* bn2b = (const float*)d_in[16];
    const float* bn2m = (const float*)d_in[17];
    const float* bn2v = (const float*)d_in[18];
    const float* bn3g = (const float*)d_in[19];
    const float* bn3b = (const float*)d_in[20];
    const float* bn3m = (const float*)d_in[21];
    const float* bn3v = (const float*)d_in[22];
    const float* dw   = (const float*)d_in[23];
    const float* db   = (const float*)d_in[24];
    float* out = (float*)d_out;

    float *MA, *MB, *XC, *Y1, *Y2, *Y3, *GM, *HH;
    unsigned *WP2, *WP3, *WP4;
    cudaGetSymbolAddress((void**)&MA, g_MA);
    cudaGetSymbolAddress((void**)&MB, g_MB);
    cudaGetSymbolAddress((void**)&XC, g_XC);
    cudaGetSymbolAddress((void**)&Y1, g_Y1);
    cudaGetSymbolAddress((void**)&Y2, g_Y2);
    cudaGetSymbolAddress((void**)&Y3, g_Y3);
    cudaGetSymbolAddress((void**)&GM, g_GM);
    cudaGetSymbolAddress((void**)&HH, g_H);
    cudaGetSymbolAddress((void**)&WP2, g_WP2);
    cudaGetSymbolAddress((void**)&WP3, g_WP3);
    cudaGetSymbolAddress((void**)&WP4, g_WP4);

    cudaFuncSetAttribute(recon_k<true>,
        cudaFuncAttributeMaxDynamicSharedMemorySize, QSH);
    cudaFuncSetAttribute(recon_k<false>,
        cudaFuncAttributeMaxDynamicSharedMemorySize, QSH);

    // weight packing + GM zero (single tiny launch)
    packall_k<<<63, 256>>>(w2, w3, w4, WP2, WP3, WP4, GM);

    // fused morphology -> XC
    morph4_k<<<dim3(4, 4, B), 256>>>(x, XC, ko, kc);

    // CNN
    conv1_k<<<dim3(254, B), 256>>>(XC, w1, b1, bn1g, bn1b, bn1m, bn1v, Y1);
    tconv2_k<<<dim3(4, 32, B), 256>>>(Y1, WP2, b2, bn2g, bn2b, bn2m, bn2v, Y2);
    tconv_k<16, 126, 126, 1><<<dim3(4, 16, B), 256>>>(
        Y2, WP3, b3, bn3g, bn3b, bn3m, bn3v, Y3);
    tconv_k<32, 124, 124, 2><<<dim3(4, 16, B), 256>>>(
        Y3, WP4, b4, nullptr, nullptr, nullptr, nullptr, GM);
    dense_k<<<1, 32>>>(GM, dw, db, HH, out + (size_t)NPIX);

    // h-maxima: 50 steps = 10 launches of 5 fused steps (first fuses marker init)
    recon_k<true><<<dim3(4, 4, B), 288, QSH>>>(XC, XC, HH, MB);
    for (int l = 1; l < 10; l++) {
        float* srcp = (l & 1) ? MB : MA;
        float* dstp = (l == 9) ? out : ((l & 1) ? MA : MB);
        recon_k<false><<<dim3(4, 4, B), 288, QSH>>>(srcp, XC, nullptr, dstp);
    }
}

// round 15
// speedup vs baseline: 1.0351x; 1.0351x over previous
#include <cuda_runtime.h>
#include <math_constants.h>

#define B 32
#define H0 256
#define W0 256
#define NPIX (B*H0*W0)
#define BN_EPS 1e-3f

typedef unsigned long long u64t;

__device__ __forceinline__ u64t pk2(float a, float b) {
    u64t r; asm("mov.b64 %0,{%1,%2};" : "=l"(r) : "f"(a), "f"(b)); return r;
}
__device__ __forceinline__ void upk2(u64t v, float& a, float& b) {
    asm("mov.b64 {%0,%1},%2;" : "=f"(a), "=f"(b) : "l"(v));
}
__device__ __forceinline__ void fma2(u64t& d, u64t a, u64t b) {
    asm("fma.rn.f32x2 %0,%1,%2,%0;" : "+l"(d) : "l"(a), "l"(b));
}
__device__ __forceinline__ unsigned tf32r(float v) {
    unsigned r; asm("cvt.rna.tf32.f32 %0,%1;" : "=r"(r) : "f"(v)); return r;
}
__device__ __forceinline__ float tf32rf(float v) {
    return __uint_as_float(tf32r(v));
}
#define MMA_TF32(d, a0,a1,a2,a3, b0,b1) \
    asm volatile("mma.sync.aligned.m16n8k8.row.col.f32.tf32.tf32.f32 " \
        "{%0,%1,%2,%3},{%4,%5,%6,%7},{%8,%9},{%0,%1,%2,%3};" \
        : "+f"((d)[0]),"+f"((d)[1]),"+f"((d)[2]),"+f"((d)[3]) \
        : "r"(a0),"r"(a1),"r"(a2),"r"(a3),"r"(b0),"r"(b1))

// ---------------- scratch ----------------
__device__ float g_MA[NPIX];
__device__ float g_MB[NPIX];
__device__ float g_XC[NPIX];
__device__ float g_Y1[(size_t)B*8*254*254];   // tf32-rounded values
__device__ float g_Y2[(size_t)B*16*126*126];  // tf32-rounded values
__device__ float g_Y3[(size_t)B*32*124*124];  // tf32-rounded values
__device__ float g_GM[B*32];
__device__ float g_H[B];
__device__ unsigned g_WP2[1152];
__device__ unsigned g_WP3[4608];
__device__ unsigned g_WP4[9216];

// ---------------- merged weight packing + GM zero (one launch) ----------------
__global__ void packall_k(const float* __restrict__ w2, const float* __restrict__ w3,
                          const float* __restrict__ w4,
                          unsigned* __restrict__ WP2, unsigned* __restrict__ WP3,
                          unsigned* __restrict__ WP4, float* __restrict__ GM) {
    int gidx = threadIdx.x + blockIdx.x*256;
    if (gidx < 1152) {
        int idx = gidx;
        int val = idx & 3; int knb = val >> 1, kkh = val & 1;
        int ln  = (idx >> 2) & 31; int lkq = ln & 3, lnr = ln >> 2;
        int tap = idx >> 7;
        int ci = lkq + 4*kkh;
        int co = knb*8 + lnr;
        WP2[idx] = tf32r(w2[tap*128 + ci*16 + co]);
    } else if (gidx < 1152 + 4608) {
        int idx = gidx - 1152;
        int val = idx & 7; int knb = val >> 1, kkh = val & 1;
        int ln  = (idx >> 3) & 31; int lkq = ln & 3, lnr = ln >> 2;
        int rest = idx >> 8;
        int cib = rest & 1; int t2 = rest >> 1;
        int tap = t2 % 9, cc = t2 / 9;
        int ci = cc*16 + cib*8 + lkq + 4*kkh;
        int co = knb*8 + lnr;
        WP3[idx] = tf32r(w3[tap*(16*32) + ci*32 + co]);
    } else if (gidx < 1152 + 4608 + 9216) {
        int idx = gidx - 5760;
        int val = idx & 7; int knb = val >> 1, kkh = val & 1;
        int ln  = (idx >> 3) & 31; int lkq = ln & 3, lnr = ln >> 2;
        int rest = idx >> 8;
        int cib = rest & 1; int t2 = rest >> 1;
        int tap = t2 % 9, cc = t2 / 9;
        int ci = cc*16 + cib*8 + lkq + 4*kkh;
        int co = knb*8 + lnr;
        WP4[idx] = tf32r(w4[tap*(32*32) + ci*32 + co]);
    } else if (gidx < 1152 + 4608 + 9216 + B*32) {
        GM[gidx - 14976] = 0.f;
    }
}

// ---------------- fused 4-pass morphology: E(ko),D(ko),D(kc),E(kc), halo 4 ----------------
#define MT 64
#define MHL 4
#define MS (MT + 2*MHL)
#define MCELL (MS*MS)
#define MNIT ((MCELL + 255)/256)
__global__ __launch_bounds__(256)
void morph4_k(const float* __restrict__ x, float* __restrict__ xc,
              const float* __restrict__ ko, const float* __restrict__ kc) {
    __shared__ float sm[2][MCELL];
    __shared__ float sk[18];
    int t = threadIdx.x;
    if (t < 18) sk[t] = (t < 9) ? ko[t] : kc[t - 9];
    int ox = blockIdx.x*MT - MHL;
    int oy = blockIdx.y*MT - MHL;
    const size_t boff = (size_t)blockIdx.z*H0*W0;

    bool inb[MNIT], inter[MNIT];
#pragma unroll
    for (int k = 0; k < MNIT; k++) {
        int i = t + k*256;
        bool ib = false, it = false;
        if (i < MCELL) {
            int ly = i / MS, lx = i % MS;
            int gy = oy + ly, gx = ox + lx;
            ib = (gy >= 0 && gy < H0 && gx >= 0 && gx < W0);
            sm[0][i] = ib ? x[boff + gy*W0 + gx] : CUDART_INF_F;
            it = (ly > 0 && ly < MS-1 && lx > 0 && lx < MS-1);
        }
        inb[k] = ib; inter[k] = it;
    }
    __syncthreads();
    int cur = 0;
#pragma unroll
    for (int op = 0; op < 4; op++) {
        const bool ero = (op == 0 || op == 3);
        const int koff = (op < 2) ? 0 : 9;
        const float nextpad = (op >= 2) ? CUDART_INF_F : -CUDART_INF_F;
#pragma unroll
        for (int k = 0; k < MNIT; k++) {
            int i = t + k*256;
            if (i < MCELL) {
                float v;
                if (!inb[k]) {
                    v = nextpad;
                } else if (inter[k]) {
                    const float* s0 = &sm[cur][i];
                    if (ero) {
                        float m = s0[-MS-1] - sk[koff + 8];
                        m = fminf(m, s0[-MS  ] - sk[koff + 7]);
                        m = fminf(m, s0[-MS+1] - sk[koff + 6]);
                        m = fminf(m, s0[-1]    - sk[koff + 5]);
                        m = fminf(m, s0[0]     - sk[koff + 4]);
                        m = fminf(m, s0[1]     - sk[koff + 3]);
                        m = fminf(m, s0[MS-1]  - sk[koff + 2]);
                        m = fminf(m, s0[MS  ]  - sk[koff + 1]);
                        m = fminf(m, s0[MS+1]  - sk[koff + 0]);
                        v = m;
                    } else {
                        float m = s0[-MS-1] + sk[koff + 0];
                        m = fmaxf(m, s0[-MS  ] + sk[koff + 1]);
                        m = fmaxf(m, s0[-MS+1] + sk[koff + 2]);
                        m = fmaxf(m, s0[-1]    + sk[koff + 3]);
                        m = fmaxf(m, s0[0]     + sk[koff + 4]);
                        m = fmaxf(m, s0[1]     + sk[koff + 5]);
                        m = fmaxf(m, s0[MS-1]  + sk[koff + 6]);
                        m = fmaxf(m, s0[MS  ]  + sk[koff + 7]);
                        m = fmaxf(m, s0[MS+1]  + sk[koff + 8]);
                        v = m;
                    }
                } else {
                    v = sm[cur][i];
                }
                sm[1-cur][i] = v;
            }
        }
        __syncthreads();
        cur ^= 1;
    }
    int tx = t & 63, tyq = t >> 6;
#pragma unroll
    for (int k = 0; k < 16; k++) {
        int r = tyq + 4*k;
        xc[boff + (size_t)(oy + MHL + r)*W0 + (ox + MHL + tx)] =
            sm[cur][(r + MHL)*MS + (tx + MHL)];
    }
}

// ---------------- conv1 (1->8) + relu + bn1, output tf32-rounded ----------------
__global__ void conv1_k(const float* __restrict__ xc, const float* __restrict__ w,
                        const float* __restrict__ bias,
                        const float* __restrict__ gg, const float* __restrict__ bb,
                        const float* __restrict__ mm, const float* __restrict__ vv,
                        float* __restrict__ out) {
    __shared__ float ws[72];
    int t = threadIdx.x;
    if (t < 72) ws[t] = w[t];
    __syncthreads();
    int y = blockIdx.x, b = blockIdx.y;
    int x = t;
    if (x >= 254) return;
    const float* base = xc + ((size_t)b*H0 + y)*W0 + x;
    u64t acc[4];
#pragma unroll
    for (int p = 0; p < 4; p++) acc[p] = pk2(bias[2*p], bias[2*p+1]);
#pragma unroll
    for (int tap = 0; tap < 9; tap++) {
        float v = base[(tap/3)*W0 + (tap%3)];
        u64t pv = pk2(v, v);
        const u64t* wq = (const u64t*)(ws + tap*8);
#pragma unroll
        for (int p = 0; p < 4; p++) fma2(acc[p], pv, wq[p]);
    }
#pragma unroll
    for (int p = 0; p < 4; p++) {
        float a0, a1; upk2(acc[p], a0, a1);
        int k0 = 2*p, k1 = 2*p+1;
        float s0 = gg[k0] * rsqrtf(vv[k0] + BN_EPS);
        float s1 = gg[k1] * rsqrtf(vv[k1] + BN_EPS);
        out[((size_t)(b*8 + k0)*254 + y)*254 + x] =
            tf32rf(s0*(fmaxf(a0,0.f) - mm[k0]) + bb[k0]);
        out[((size_t)(b*8 + k1)*254 + y)*254 + x] =
            tf32rf(s1*(fmaxf(a1,0.f) - mm[k1]) + bb[k1]);
    }
}

// ---------------- conv3/conv4: tensor tf32, TW=32, CO=32 ----------------
// Inputs already tf32-rounded by producer -> staging is a plain bit copy.
// MODE 1: store tf32(bn(relu(conv+b)))   MODE 2: global atomic max of relu(conv+b)
template<int CI, int HIN, int WIN, int MODE>
__global__ __launch_bounds__(256)
void tconv_k(const float* __restrict__ gin, const unsigned* __restrict__ gwp,
             const float* __restrict__ gb,
             const float* __restrict__ bng, const float* __restrict__ bnb,
             const float* __restrict__ bnm, const float* __restrict__ bnv,
             float* __restrict__ gout) {
    constexpr int CO = 32;
    constexpr int HOUT = HIN - 2, WOUT = WIN - 2;
    constexpr int CC  = 16;
    constexpr int NCH = CI / CC;
    constexpr int STR = 36, PLANE = 360;

    __shared__ __align__(16) unsigned in_s[CC*PLANE];
    __shared__ __align__(16) unsigned wp_s[4608];
    __shared__ float smax[CO];

    int tid = threadIdx.x;
    int warp = tid >> 5, lane = tid & 31;
    int kq = lane & 3, nr = lane >> 2;
    int ox0 = blockIdx.x * 32, oy0 = blockIdx.y * 8;
    int b = blockIdx.z;

    const bool interior = (oy0 + 10 <= HIN) && (ox0 + 34 <= WIN);

    if (MODE == 2 && tid < CO) smax[tid] = 0.f;

    float acc[2][4][4];
#pragma unroll
    for (int j = 0; j < 2; j++)
#pragma unroll
        for (int nb = 0; nb < 4; nb++)
#pragma unroll
            for (int q = 0; q < 4; q++) acc[j][nb][q] = 0.f;

    for (int cc = 0; cc < NCH; cc++) {
        __syncthreads();
        for (int i = tid; i < 1152; i += 256)
            *(uint4*)&wp_s[i*4] = __ldg((const uint4*)(gwp + cc*4608 + i*4));
        if (interior) {
#pragma unroll
            for (int it = 0; it < 20; it++) {
                int rowid = it*8 + warp;
                int ci = rowid / 10, yy = rowid - ci*10;
                if (lane < 17) {
                    uint2 g = *((const uint2*)(gin +
                        ((size_t)(b*CI + cc*CC + ci)*HIN + oy0 + yy)*WIN + ox0) + lane);
                    *(uint2*)&in_s[ci*PLANE + yy*STR + lane*2] = g;
                }
            }
        } else {
            for (int idx = tid; idx < CC*340; idx += 256) {
                int ci = idx / 340, rem = idx % 340;
                int yy = rem / 34, xx = rem % 34;
                int gy = oy0 + yy, gx = ox0 + xx;
                float v = 0.f;
                if (gy < HIN && gx < WIN)
                    v = gin[((size_t)(b*CI + cc*CC + ci)*HIN + gy)*WIN + gx];
                in_s[ci*PLANE + yy*STR + xx] = __float_as_uint(v);
            }
        }
        __syncthreads();
#pragma unroll
        for (int tap = 0; tap < 9; tap++) {
            const int dy = tap/3, dx = tap%3;
#pragma unroll
            for (int cib = 0; cib < 2; cib++) {
                const uint4* wq = (const uint4*)(wp_s + ((tap*2 + cib)*32 + lane)*8);
                uint4 b01 = wq[0];
                uint4 b23 = wq[1];
                const unsigned* ia = in_s + (cib*8 + kq)*PLANE + (warp+dy)*STR + dx + nr;
#pragma unroll
                for (int j = 0; j < 2; j++) {
                    unsigned a0 = ia[j*16];
                    unsigned a1 = ia[j*16 + 8];
                    unsigned a2 = ia[j*16 + 4*PLANE];
                    unsigned a3 = ia[j*16 + 4*PLANE + 8];
                    MMA_TF32(acc[j][0], a0, a1, a2, a3, b01.x, b01.y);
                    MMA_TF32(acc[j][1], a0, a1, a2, a3, b01.z, b01.w);
                    MMA_TF32(acc[j][2], a0, a1, a2, a3, b23.x, b23.y);
                    MMA_TF32(acc[j][3], a0, a1, a2, a3, b23.z, b23.w);
                }
            }
        }
    }

    int y = oy0 + warp;
    float biA[4], biB[4];
#pragma unroll
    for (int nb = 0; nb < 4; nb++) {
        biA[nb] = gb[nb*8 + 2*kq];
        biB[nb] = gb[nb*8 + 2*kq + 1];
    }

    if (MODE == 2) {
        float lm[4][2];
#pragma unroll
        for (int nb = 0; nb < 4; nb++) { lm[nb][0] = 0.f; lm[nb][1] = 0.f; }
        if (y < HOUT) {
#pragma unroll
            for (int j = 0; j < 2; j++) {
                int xA = ox0 + j*16 + nr;
                int xB = xA + 8;
#pragma unroll
                for (int nb = 0; nb < 4; nb++) {
                    if (xA < WOUT) {
                        lm[nb][0] = fmaxf(lm[nb][0], acc[j][nb][0] + biA[nb]);
                        lm[nb][1] = fmaxf(lm[nb][1], acc[j][nb][1] + biB[nb]);
                    }
                    if (xB < WOUT) {
                        lm[nb][0] = fmaxf(lm[nb][0], acc[j][nb][2] + biA[nb]);
                        lm[nb][1] = fmaxf(lm[nb][1], acc[j][nb][3] + biB[nb]);
                    }
                }
            }
        }
#pragma unroll
        for (int nb = 0; nb < 4; nb++) {
            atomicMax((int*)&smax[nb*8 + 2*kq],     __float_as_int(fmaxf(lm[nb][0], 0.f)));
            atomicMax((int*)&smax[nb*8 + 2*kq + 1], __float_as_int(fmaxf(lm[nb][1], 0.f)));
        }
        __syncthreads();
        if (tid < CO)
            atomicMax((int*)&gout[b*CO + tid], __float_as_int(smax[tid]));
    } else {
        if (y < HOUT) {
#pragma unroll
            for (int nb = 0; nb < 4; nb++) {
                int coA = nb*8 + 2*kq, coB = coA + 1;
                float scA = bng[coA] * rsqrtf(bnv[coA] + BN_EPS);
                float scB = bng[coB] * rsqrtf(bnv[coB] + BN_EPS);
                float sbA = bnb[coA], sbB = bnb[coB];
                float smA = bnm[coA], smB = bnm[coB];
                float* pA = gout + ((size_t)(b*CO + coA)*HOUT + y)*WOUT;
                float* pB = gout + ((size_t)(b*CO + coB)*HOUT + y)*WOUT;
#pragma unroll
                for (int j = 0; j < 2; j++) {
                    int xA = ox0 + j*16 + nr;
                    int xB = xA + 8;
                    if (xA < WOUT) {
                        pA[xA] = tf32rf(scA*(fmaxf(acc[j][nb][0] + biA[nb], 0.f) - smA) + sbA);
                        pB[xA] = tf32rf(scB*(fmaxf(acc[j][nb][1] + biB[nb], 0.f) - smB) + sbB);
                    }
                    if (xB < WOUT) {
                        pA[xB] = tf32rf(scA*(fmaxf(acc[j][nb][2] + biA[nb], 0.f) - smA) + sbA);
                        pB[xB] = tf32rf(scB*(fmaxf(acc[j][nb][3] + biB[nb], 0.f) - smB) + sbB);
                    }
                }
            }
        }
    }
}

// ---------------- conv2 tensor: CI=8, CO=16, TW=64, fused maxpool2+bn, output rounded ----------------
#define T2STR   68
#define T2PLANE 680
__global__ __launch_bounds__(256)
void tconv2_k(const float* __restrict__ gin, const unsigned* __restrict__ gwp,
              const float* __restrict__ gb,
              const float* __restrict__ bng, const float* __restrict__ bnb,
              const float* __restrict__ bnm, const float* __restrict__ bnv,
              float* __restrict__ gout) {
    constexpr int CI = 8, CO = 16;
    constexpr int HIN = 254, WIN = 254;
    constexpr int HOUT = 252, WOUT = 252;
    constexpr int LW = 66;

    __shared__ __align__(16) unsigned shm2[8192];
    __shared__ __align__(16) unsigned wp_s[1152];
    unsigned* in_s = shm2;
    float* pool_s  = (float*)shm2;

    int tid = threadIdx.x;
    int warp = tid >> 5, lane = tid & 31;
    int kq = lane & 3, nr = lane >> 2;
    int ox0 = blockIdx.x * 64, oy0 = blockIdx.y * 8;
    int b = blockIdx.z;

    const bool interior = (oy0 + 10 <= HIN) && (ox0 + 66 <= WIN);

    float acc[4][2][4];
#pragma unroll
    for (int j = 0; j < 4; j++)
#pragma unroll
        for (int nb = 0; nb < 2; nb++)
#pragma unroll
            for (int q = 0; q < 4; q++) acc[j][nb][q] = 0.f;

    for (int i = tid; i < 288; i += 256)
        if (i < 288) *(uint4*)&wp_s[i*4] = __ldg((const uint4*)(gwp + i*4));

    if (interior) {
#pragma unroll
        for (int it = 0; it < 10; it++) {
            int rowid = it*8 + warp;
            int ci = rowid / 10, yy = rowid - ci*10;
            const float* gr = gin + ((size_t)(b*CI + ci)*HIN + oy0 + yy)*WIN + ox0;
            unsigned* sr = in_s + ci*T2PLANE + yy*T2STR;
            *(uint2*)&sr[lane*2] = *(const uint2*)(gr + lane*2);
            if (lane == 0) *(uint2*)&sr[64] = *(const uint2*)(gr + 64);
        }
    } else {
        for (int idx = tid; idx < CI*10*LW; idx += 256) {
            int ci = idx / (10*LW), rem = idx % (10*LW);
            int yy = rem / LW, xx = rem % LW;
            int gy = oy0 + yy, gx = ox0 + xx;
            float v = 0.f;
            if (gy < HIN && gx < WIN)
                v = gin[((size_t)(b*CI + ci)*HIN + gy)*WIN + gx];
            in_s[ci*T2PLANE + yy*T2STR + xx] = __float_as_uint(v);
        }
    }
    __syncthreads();
#pragma unroll
    for (int tap = 0; tap < 9; tap++) {
        const int dy = tap/3, dx = tap%3;
        uint4 bq = *(const uint4*)(wp_s + (tap*32 + lane)*4);
        const unsigned* ia = in_s + kq*T2PLANE + (warp+dy)*T2STR + dx + nr;
#pragma unroll
        for (int j = 0; j < 4; j++) {
            unsigned a0 = ia[j*16];
            unsigned a1 = ia[j*16 + 8];
            unsigned a2 = ia[j*16 + 4*T2PLANE];
            unsigned a3 = ia[j*16 + 4*T2PLANE + 8];
            MMA_TF32(acc[j][0], a0, a1, a2, a3, bq.x, bq.y);
            MMA_TF32(acc[j][1], a0, a1, a2, a3, bq.z, bq.w);
        }
    }

    float biA[2], biB[2];
#pragma unroll
    for (int nb = 0; nb < 2; nb++) {
        biA[nb] = gb[nb*8 + 2*kq];
        biB[nb] = gb[nb*8 + 2*kq + 1];
    }
    __syncthreads();
#pragma unroll
    for (int j = 0; j < 4; j++) {
        int xA = j*16 + nr, xB = xA + 8;
#pragma unroll
        for (int nb = 0; nb < 2; nb++) {
            int coA = nb*8 + 2*kq, coB = coA + 1;
            pool_s[warp*1024 + xA*16 + coA] = fmaxf(acc[j][nb][0] + biA[nb], 0.f);
            pool_s[warp*1024 + xA*16 + coB] = fmaxf(acc[j][nb][1] + biB[nb], 0.f);
            pool_s[warp*1024 + xB*16 + coA] = fmaxf(acc[j][nb][2] + biA[nb], 0.f);
            pool_s[warp*1024 + xB*16 + coB] = fmaxf(acc[j][nb][3] + biB[nb], 0.f);
        }
    }
    __syncthreads();

#pragma unroll
    for (int pid = tid; pid < 2048; pid += 256) {
        int co = pid & 15;
        int px = (pid >> 4) & 31;
        int py = pid >> 9;
        int base = (2*py)*1024 + (2*px)*16 + co;
        float v = fmaxf(fmaxf(pool_s[base], pool_s[base+16]),
                        fmaxf(pool_s[base+1024], pool_s[base+1040]));
        int gpy = (oy0 >> 1) + py;
        int gpx = (ox0 >> 1) + px;
        if (gpy < HOUT/2 && gpx < WOUT/2) {
            float sc = bng[co] * rsqrtf(bnv[co] + BN_EPS);
            v = sc*(v - bnm[co]) + bnb[co];
            gout[((size_t)(b*CO + co)*(HOUT/2) + gpy)*(WOUT/2) + gpx] = tf32rf(v);
        }
    }
}

// ---------------- dense ----------------
__global__ void dense_k(const float* __restrict__ gm, const float* __restrict__ dw,
                        const float* __restrict__ db, float* __restrict__ h,
                        float* __restrict__ out_tail) {
    int b = threadIdx.x;
    if (b >= B) return;
    float s = db[0];
#pragma unroll
    for (int c = 0; c < 32; c++) s = fmaf(gm[b*32 + c], dw[c], s);
    h[b] = s;
    out_tail[b] = s;
}

// ---------------- geodesic reconstruction: 5 fused steps, 64x64 tile (R8/R13 proven) ----------------
#define RK 5
#define RT 64
#define RS (RT + 2*RK)
#define RCELL (RS*RS)
#define RNIT ((RCELL + 255)/256)
template<bool INIT>
__global__ __launch_bounds__(256)
void recon_k(const float* __restrict__ src, const float* __restrict__ mask,
             const float* __restrict__ h, float* __restrict__ dst) {
    __shared__ float sm[2][RCELL];
    int t = threadIdx.x;
    int ox = blockIdx.x*RT - RK;
    int oy = blockIdx.y*RT - RK;
    const size_t boff = (size_t)blockIdx.z*H0*W0;
    const float hv = INIT ? h[blockIdx.z] : 0.f;

    float mk[RNIT];
    bool  inter[RNIT];
#pragma unroll
    for (int k = 0; k < RNIT; k++) {
        int i = t + k*256;
        float sv = -CUDART_INF_F, mv = -CUDART_INF_F;
        bool it = false;
        if (i < RCELL) {
            int ly = i / RS, lx = i % RS;
            int gy = oy + ly, gx = ox + lx;
            if (gy >= 0 && gy < H0 && gx >= 0 && gx < W0) {
                mv = mask[boff + gy*W0 + gx];
                sv = INIT ? (mv - hv) : src[boff + gy*W0 + gx];
            }
            sm[0][i] = sv;
            it = (ly > 0 && ly < RS-1 && lx > 0 && lx < RS-1);
        }
        mk[k] = mv;
        inter[k] = it;
    }
    __syncthreads();
    int cur = 0;
#pragma unroll
    for (int step = 0; step < RK; step++) {
#pragma unroll
        for (int k = 0; k < RNIT; k++) {
            int i = t + k*256;
            if (i < RCELL) {
                float v;
                if (inter[k]) {
                    const float* s0 = &sm[cur][i];
                    float a = fmaxf(fmaxf(s0[-RS-1], s0[-RS]), s0[-RS+1]);
                    float c = fmaxf(fmaxf(s0[-1],    s0[0]),   s0[1]);
                    float d = fmaxf(fmaxf(s0[RS-1],  s0[RS]),  s0[RS+1]);
                    v = fminf(fmaxf(fmaxf(a, c), d), mk[k]);
                } else {
                    v = sm[cur][i];
                }
                sm[1-cur][i] = v;
            }
        }
        __syncthreads();
        cur ^= 1;
    }
    int tx = t & 63, tyq = t >> 6;
#pragma unroll
    for (int k = 0; k < 16; k++) {
        int r = tyq + 4*k;
        dst[boff + (size_t)(oy + RK + r)*W0 + (ox + RK + tx)] =
            sm[cur][(r + RK)*RS + (tx + RK)];
    }
}

// ---------------- launch ----------------
extern "C" void kernel_launch(void* const* d_in, const int* in_sizes, int n_in,
                              void* d_out, int out_size) {
    const float* x    = (const float*)d_in[0];
    const float* ko   = (const float*)d_in[1];
    const float* kc   = (const float*)d_in[2];
    const float* w1   = (const float*)d_in[3];
    const float* b1   = (const float*)d_in[4];
    const float* w2   = (const float*)d_in[5];
    const float* b2   = (const float*)d_in[6];
    const float* w3   = (const float*)d_in[7];
    const float* b3   = (const float*)d_in[8];
    const float* w4   = (const float*)d_in[9];
    const float* b4   = (const float*)d_in[10];
    const float* bn1g = (const float*)d_in[11];
    const float* bn1b = (const float*)d_in[12];
    const float* bn1m = (const float*)d_in[13];
    const float* bn1v = (const float*)d_in[14];
    const float* bn2g = (const float*)d_in[15];
    const float* bn2b = (const float*)d_in[16];
    const float* bn2m = (const float*)d_in[17];
    const float* bn2v = (const float*)d_in[18];
    const float* bn3g = (const float*)d_in[19];
    const float* bn3b = (const float*)d_in[20];
    const float* bn3m = (const float*)d_in[21];
    const float* bn3v = (const float*)d_in[22];
    const float* dw   = (const float*)d_in[23];
    const float* db   = (const float*)d_in[24];
    float* out = (float*)d_out;

    float *MA, *MB, *XC, *Y1, *Y2, *Y3, *GM, *HH;
    unsigned *WP2, *WP3, *WP4;
    cudaGetSymbolAddress((void**)&MA, g_MA);
    cudaGetSymbolAddress((void**)&MB, g_MB);
    cudaGetSymbolAddress((void**)&XC, g_XC);
    cudaGetSymbolAddress((void**)&Y1, g_Y1);
    cudaGetSymbolAddress((void**)&Y2, g_Y2);
    cudaGetSymbolAddress((void**)&Y3, g_Y3);
    cudaGetSymbolAddress((void**)&GM, g_GM);
    cudaGetSymbolAddress((void**)&HH, g_H);
    cudaGetSymbolAddress((void**)&WP2, g_WP2);
    cudaGetSymbolAddress((void**)&WP3, g_WP3);
    cudaGetSymbolAddress((void**)&WP4, g_WP4);

    // weight packing + GM zero (single tiny launch)
    packall_k<<<63, 256>>>(w2, w3, w4, WP2, WP3, WP4, GM);

    // fused morphology -> XC
    morph4_k<<<dim3(4, 4, B), 256>>>(x, XC, ko, kc);

    // CNN
    conv1_k<<<dim3(254, B), 256>>>(XC, w1, b1, bn1g, bn1b, bn1m, bn1v, Y1);
    tconv2_k<<<dim3(4, 32, B), 256>>>(Y1, WP2, b2, bn2g, bn2b, bn2m, bn2v, Y2);
    tconv_k<16, 126, 126, 1><<<dim3(4, 16, B), 256>>>(
        Y2, WP3, b3, bn3g, bn3b, bn3m, bn3v, Y3);
    tconv_k<32, 124, 124, 2><<<dim3(4, 16, B), 256>>>(
        Y3, WP4, b4, nullptr, nullptr, nullptr, nullptr, GM);
    dense_k<<<1, 32>>>(GM, dw, db, HH, out + (size_t)NPIX);

    // h-maxima: 50 steps = 10 launches of 5 fused steps (first fuses marker init)
    recon_k<true><<<dim3(4, 4, B), 256>>>(XC, XC, HH, MB);
    for (int l = 1; l < 10; l++) {
        float* srcp = (l & 1) ? MB : MA;
        float* dstp = (l == 9) ? out : ((l & 1) ? MA : MB);
        recon_k<false><<<dim3(4, 4, B), 256>>>(srcp, XC, nullptr, dstp);
    }
}